// round 12
// baseline (speedup 1.0000x reference)
#include <cuda_runtime.h>
#include <cstdint>

typedef unsigned long long u64;

#define Bn    16
#define R     360
#define RPAD  384    // padded row length (float2 units) for u/v scratch
#define GRID  576
#define K1_CTAS 360

// Scratch: u2[b][dpair k][i] = (u[i][2k], u[i][2k+1]) packed fp32x2; same for v (v includes +b_out)
__device__ u64 g_u2[Bn * 32 * RPAD];
__device__ u64 g_v2[Bn * 32 * RPAD];
__device__ u64 g_bar;   // monotonic grid-barrier counter (zero-init, never reset)

// ---------- packed fp32x2 helpers (sm_100+) ----------
__device__ __forceinline__ u64 pack2(float x, float y) {
    u64 d; asm("mov.b64 %0, {%1, %2};" : "=l"(d) : "f"(x), "f"(y)); return d;
}
__device__ __forceinline__ void unpack2(u64 a, float &x, float &y) {
    asm("mov.b64 {%0, %1}, %2;" : "=f"(x), "=f"(y) : "l"(a));
}
__device__ __forceinline__ void ffma2(u64 &d, u64 a, u64 b) {
    asm("fma.rn.f32x2 %0, %1, %2, %0;" : "+l"(d) : "l"(a), "l"(b));
}
// acc += w * relu(u+v)
__device__ __forceinline__ void relu_dot2(u64 &acc, u64 u, u64 v, u64 w) {
    u64 s;
    asm("add.rn.f32x2 %0, %1, %2;" : "=l"(s) : "l"(u), "l"(v));
    float lo, hi; unpack2(s, lo, hi);
    lo = fmaxf(lo, 0.0f); hi = fmaxf(hi, 0.0f);
    s = pack2(lo, hi);
    ffma2(acc, s, w);
}

// Shared-memory union: phase0 (GEMM) overlays phase1 (pairwise)
struct SmemP0 {
    u64 xs[16][33];
    u64 Wu[32][64];
    u64 Wv[32][64];
};
struct SmemP1 {
    u64 Us[32][64];
    u64 Vs[32][64];
    u64 Ww[32];
};
union SmemU { SmemP0 p0; SmemP1 p1; };

// ============================================================================
// Fused kernel: phase0 = u/v GEMM on CTAs [0,360); grid barrier; phase1 = pairwise.
// 576 CTAs co-resident at 4 CTAs/SM (148*4 = 592 slots), single launch.
// ============================================================================
__global__ __launch_bounds__(256, 4) void fused_all(
    const float* __restrict__ x,      // [5760][64]
    const float* __restrict__ Wout,   // [128][64]
    const float* __restrict__ bout,   // [64]
    const float* __restrict__ Wcat,   // [64]
    const float* __restrict__ bcat,   // [1]
    float* __restrict__ out)          // [16*360*360]
{
    __shared__ SmemU sm;
    const int t = threadIdx.x;
    const int c = blockIdx.x;

    // ---------------- Phase 0: k1 body (R10-proven) on CTAs < 360 ----------------
    if (c < K1_CTAS) {
        const int row0 = c * 16;
        {
            const int cc = t & 63, p0 = t >> 6;
            #pragma unroll
            for (int p = p0; p < 32; p += 4) {
                sm.p0.Wu[p][cc] = pack2(Wout[(2 * p) * 64 + cc],      Wout[(2 * p + 1) * 64 + cc]);
                sm.p0.Wv[p][cc] = pack2(Wout[(64 + 2 * p) * 64 + cc], Wout[(65 + 2 * p) * 64 + cc]);
            }
        }
        {
            const u64* x2 = (const u64*)x;
            #pragma unroll
            for (int idx = t; idx < 16 * 32; idx += 256) {
                const int r = idx >> 5, lane = idx & 31;
                sm.p0.xs[r][lane] = x2[(size_t)(row0 + r) * 32 + lane];
            }
        }
        __syncthreads();

        const int row  = t & 15;
        const int g    = t >> 4;
        const int ccol = (g & 7) * 8;
        const bool isv = (g >= 8);
        const u64 (*Ws)[64] = isv ? sm.p0.Wv : sm.p0.Wu;

        u64 acc[8];
        #pragma unroll
        for (int j = 0; j < 8; j++) acc[j] = 0ull;

        #pragma unroll
        for (int p = 0; p < 32; p++) {
            const u64 xv = sm.p0.xs[row][p];
            ulonglong2 wa = *(const ulonglong2*)&Ws[p][ccol];
            ulonglong2 wb = *(const ulonglong2*)&Ws[p][ccol + 2];
            ulonglong2 wc = *(const ulonglong2*)&Ws[p][ccol + 4];
            ulonglong2 wd = *(const ulonglong2*)&Ws[p][ccol + 6];
            ffma2(acc[0], xv, wa.x);  ffma2(acc[1], xv, wa.y);
            ffma2(acc[2], xv, wb.x);  ffma2(acc[3], xv, wb.y);
            ffma2(acc[4], xv, wc.x);  ffma2(acc[5], xv, wc.y);
            ffma2(acc[6], xv, wd.x);  ffma2(acc[7], xv, wd.y);
        }

        const int grow = row0 + row;
        const int bb = grow / 360;
        const int i = grow - bb * 360;
        u64* gdst = isv ? g_v2 : g_u2;
        #pragma unroll
        for (int j = 0; j < 8; j += 2) {
            float l0, h0, l1, h1;
            unpack2(acc[j],     l0, h0);
            unpack2(acc[j + 1], l1, h1);
            float v0 = l0 + h0, v1 = l1 + h1;
            const int dd = ccol + j;
            if (isv) { v0 += __ldg(&bout[dd]); v1 += __ldg(&bout[dd + 1]); }
            gdst[(bb * 32 + (dd >> 1)) * RPAD + i] = pack2(v0, v1);
        }
    }

    // ---------------- Grid barrier (replay-safe monotonic counter) ----------------
    __threadfence();
    __syncthreads();
    if (t == 0) {
        u64 old = atomicAdd(&g_bar, 1ull);
        u64 target = (old / (u64)GRID + 1ull) * (u64)GRID;
        long long tstart = clock64();
        while (true) {
            u64 cur;
            asm volatile("ld.acquire.gpu.u64 %0, [%1];" : "=l"(cur) : "l"(&g_bar) : "memory");
            if (cur >= target) break;
            if (clock64() - tstart > 400000000ll) break;   // escape hatch (never in normal op)
            __nanosleep(128);
        }
    }
    __syncthreads();

    // ---------------- Phase 1: k2 body (R10-proven) on all 576 CTAs ----------------
    const int b   = c / 36;
    const int rem = c - b * 36;
    const int s0  = (rem % 6) * 64;
    const int r0  = (rem / 6) * 64;

    {
        const int cc = t & 63, k0 = t >> 6;
        const u64* gu = g_u2 + b * 32 * RPAD + s0 + cc;
        const u64* gv = g_v2 + b * 32 * RPAD + r0 + cc;
        #pragma unroll
        for (int k = k0; k < 32; k += 4) {
            sm.p1.Us[k][cc] = gu[k * RPAD];
            sm.p1.Vs[k][cc] = gv[k * RPAD];
        }
        if (t < 32) sm.p1.Ww[t] = ((const u64*)Wcat)[t];
    }
    __syncthreads();

    const int lane = t & 31;       // sends 2*lane, 2*lane+1 (conflict-free LDS.128)
    const int wg   = t >> 5;       // recs 8*wg .. 8*wg+7 (broadcast LDS.128)

    u64 acc[8][2];
    #pragma unroll
    for (int i = 0; i < 8; i++) { acc[i][0] = 0ull; acc[i][1] = 0ull; }

    #pragma unroll 8
    for (int k = 0; k < 32; k++) {
        const u64 w2 = sm.p1.Ww[k];
        ulonglong2 ua = *(const ulonglong2*)&sm.p1.Us[k][2 * lane];
        u64 vv[8];
        #pragma unroll
        for (int q = 0; q < 4; q++) {
            ulonglong2 va = *(const ulonglong2*)&sm.p1.Vs[k][8 * wg + 2 * q];
            vv[2 * q] = va.x; vv[2 * q + 1] = va.y;
        }
        #pragma unroll
        for (int i = 0; i < 8; i++) {
            relu_dot2(acc[i][0], ua.x, vv[i], w2);
            relu_dot2(acc[i][1], ua.y, vv[i], w2);
        }
    }

    const float bc = __ldg(bcat);
    const int s = s0 + 2 * lane;
    if (s < R) {
        #pragma unroll
        for (int i = 0; i < 8; i++) {
            const int rec = r0 + 8 * wg + i;
            if (rec < R) {
                float l0, h0, l1, h1;
                unpack2(acc[i][0], l0, h0);
                unpack2(acc[i][1], l1, h1);
                float2 o;
                o.x = fmaxf(l0 + h0 + bc, 0.0f);
                o.y = fmaxf(l1 + h1 + bc, 0.0f);
                *(float2*)&out[((size_t)(b * R + rec)) * R + s] = o;
            }
        }
    }
}

extern "C" void kernel_launch(void* const* d_in, const int* in_sizes, int n_in,
                              void* d_out, int out_size) {
    (void)in_sizes; (void)n_in; (void)out_size;
    const float* x    = (const float*)d_in[0];  // (16,360,64)
    const float* Wout = (const float*)d_in[1];  // (128,64)
    const float* bout = (const float*)d_in[2];  // (64)
    const float* Wcat = (const float*)d_in[3];  // (64,1)
    const float* bcat = (const float*)d_in[4];  // (1)
    float* out = (float*)d_out;                 // (16,360,360,1) fp32

    // Hint enough smem carveout for 4 CTAs/SM x 36.5KB (idempotent host call)
    static bool configured = false;
    if (!configured) {
        cudaFuncSetAttribute(fused_all, cudaFuncAttributePreferredSharedMemoryCarveout, 66);
        configured = true;
    }

    fused_all<<<GRID, 256>>>(x, Wout, bout, Wcat, bcat, out);
}

// round 13
// speedup vs baseline: 1.0849x; 1.0849x over previous
#include <cuda_runtime.h>
#include <cstdint>

typedef unsigned long long u64;

#define Bn   16
#define R    360
#define RPAD 384   // padded row length (float2 units) for u/v scratch

// Scratch: u2[b][dpair k][i] = (u[i][2k], u[i][2k+1]) packed fp32x2; same for v (v includes +b_out)
__device__ u64 g_u2[Bn * 32 * RPAD];
__device__ u64 g_v2[Bn * 32 * RPAD];

// ---------- packed fp32x2 helpers (sm_100+) ----------
__device__ __forceinline__ u64 pack2(float x, float y) {
    u64 d; asm("mov.b64 %0, {%1, %2};" : "=l"(d) : "f"(x), "f"(y)); return d;
}
__device__ __forceinline__ void unpack2(u64 a, float &x, float &y) {
    asm("mov.b64 {%0, %1}, %2;" : "=f"(x), "=f"(y) : "l"(a));
}
__device__ __forceinline__ void ffma2(u64 &d, u64 a, u64 b) {
    asm("fma.rn.f32x2 %0, %1, %2, %0;" : "+l"(d) : "l"(a), "l"(b));
}
// acc += w * relu(u+v)
__device__ __forceinline__ void relu_dot2(u64 &acc, u64 u, u64 v, u64 w) {
    u64 s;
    asm("add.rn.f32x2 %0, %1, %2;" : "=l"(s) : "l"(u), "l"(v));
    float lo, hi; unpack2(s, lo, hi);
    lo = fmaxf(lo, 0.0f); hi = fmaxf(hi, 0.0f);
    s = pack2(lo, hi);
    ffma2(acc, s, w);
}

// ============================================================================
// Kernel 1 (R10-proven): u = x @ Wout[0:64], v = x @ Wout[64:128] + b_out
// 360 blocks x 16 rows, 3 CTAs/SM -> single co-resident wave.
// ============================================================================
__global__ __launch_bounds__(256, 3) void k1_uv(
    const float* __restrict__ x,      // [5760][64]
    const float* __restrict__ Wout,   // [128][64]
    const float* __restrict__ bout)   // [64]
{
    __shared__ u64 xs[16][33];
    __shared__ u64 Wu[32][64];
    __shared__ u64 Wv[32][64];

    const int t = threadIdx.x;
    const int row0 = blockIdx.x * 16;

    {
        const int c = t & 63, p0 = t >> 6;
        #pragma unroll
        for (int p = p0; p < 32; p += 4) {
            Wu[p][c] = pack2(Wout[(2 * p) * 64 + c],      Wout[(2 * p + 1) * 64 + c]);
            Wv[p][c] = pack2(Wout[(64 + 2 * p) * 64 + c], Wout[(65 + 2 * p) * 64 + c]);
        }
    }
    {
        const u64* x2 = (const u64*)x;
        #pragma unroll
        for (int idx = t; idx < 16 * 32; idx += 256) {
            const int r = idx >> 5, lane = idx & 31;
            xs[r][lane] = x2[(size_t)(row0 + r) * 32 + lane];
        }
    }
    __syncthreads();

    const int row  = t & 15;
    const int g    = t >> 4;
    const int ccol = (g & 7) * 8;     // columns ccol..ccol+7
    const bool isv = (g >= 8);
    const u64 (*Ws)[64] = isv ? Wv : Wu;

    u64 acc[8];
    #pragma unroll
    for (int j = 0; j < 8; j++) acc[j] = 0ull;

    #pragma unroll
    for (int p = 0; p < 32; p++) {
        const u64 xv = xs[row][p];
        ulonglong2 wa = *(const ulonglong2*)&Ws[p][ccol];
        ulonglong2 wb = *(const ulonglong2*)&Ws[p][ccol + 2];
        ulonglong2 wc = *(const ulonglong2*)&Ws[p][ccol + 4];
        ulonglong2 wd = *(const ulonglong2*)&Ws[p][ccol + 6];
        ffma2(acc[0], xv, wa.x);  ffma2(acc[1], xv, wa.y);
        ffma2(acc[2], xv, wb.x);  ffma2(acc[3], xv, wb.y);
        ffma2(acc[4], xv, wc.x);  ffma2(acc[5], xv, wc.y);
        ffma2(acc[6], xv, wd.x);  ffma2(acc[7], xv, wd.y);
    }

    const int grow = row0 + row;
    const int bb = grow / 360;
    const int i = grow - bb * 360;
    u64* gdst = isv ? g_v2 : g_u2;
    #pragma unroll
    for (int j = 0; j < 8; j += 2) {
        float l0, h0, l1, h1;
        unpack2(acc[j],     l0, h0);
        unpack2(acc[j + 1], l1, h1);
        float v0 = l0 + h0, v1 = l1 + h1;      // d = ccol+j, ccol+j+1
        const int dd = ccol + j;
        if (isv) { v0 += __ldg(&bout[dd]); v1 += __ldg(&bout[dd + 1]); }
        gdst[(bb * 32 + (dd >> 1)) * RPAD + i] = pack2(v0, v1);
    }

#if __CUDA_ARCH__ >= 900
    cudaTriggerProgrammaticLaunchCompletion();
#endif
}

// ============================================================================
// Kernel 2 (R10-proven body). PDL: all non-dependent prologue (Ww fill, bcat,
// address setup) runs BEFORE cudaGridDependencySynchronize().
// ============================================================================
__global__ __launch_bounds__(256, 4) void k2_pair(
    const float* __restrict__ Wcat,   // [64]  (input, not produced by k1)
    const float* __restrict__ bcat,   // [1]
    float* __restrict__ out)          // [16*360*360]
{
    __shared__ u64 Us[32][64];    // [dpair][send]
    __shared__ u64 Vs[32][64];    // [dpair][rec]
    __shared__ u64 Ww[32];        // packed Wcat pairs

    const int t = threadIdx.x;
    const int b  = blockIdx.z;
    const int s0 = blockIdx.x * 64;
    const int r0 = blockIdx.y * 64;

    // ---- Non-dependent prologue (overlaps k1 execution under PDL) ----
    if (t < 32) Ww[t] = ((const u64*)Wcat)[t];
    const float bc = __ldg(bcat);
    const int c = t & 63, k0 = t >> 6;
    const u64* gu = g_u2 + b * 32 * RPAD + s0 + c;
    const u64* gv = g_v2 + b * 32 * RPAD + r0 + c;

#if __CUDA_ARCH__ >= 900
    cudaGridDependencySynchronize();   // wait only here for k1's u/v
#endif

    #pragma unroll
    for (int k = k0; k < 32; k += 4) {
        Us[k][c] = gu[k * RPAD];
        Vs[k][c] = gv[k * RPAD];
    }
    __syncthreads();

    const int lane = t & 31;       // sends 2*lane, 2*lane+1 (conflict-free LDS.128)
    const int wg   = t >> 5;       // recs 8*wg .. 8*wg+7 (broadcast LDS.128)

    u64 acc[8][2];
    #pragma unroll
    for (int i = 0; i < 8; i++) { acc[i][0] = 0ull; acc[i][1] = 0ull; }

    #pragma unroll 8
    for (int k = 0; k < 32; k++) {
        const u64 w2 = Ww[k];
        ulonglong2 ua = *(const ulonglong2*)&Us[k][2 * lane];
        u64 vv[8];
        #pragma unroll
        for (int q = 0; q < 4; q++) {
            ulonglong2 va = *(const ulonglong2*)&Vs[k][8 * wg + 2 * q];
            vv[2 * q] = va.x; vv[2 * q + 1] = va.y;
        }
        #pragma unroll
        for (int i = 0; i < 8; i++) {
            relu_dot2(acc[i][0], ua.x, vv[i], w2);
            relu_dot2(acc[i][1], ua.y, vv[i], w2);
        }
    }

    const int s = s0 + 2 * lane;
    if (s < R) {
        #pragma unroll
        for (int i = 0; i < 8; i++) {
            const int rec = r0 + 8 * wg + i;
            if (rec < R) {
                float l0, h0, l1, h1;
                unpack2(acc[i][0], l0, h0);
                unpack2(acc[i][1], l1, h1);
                float2 o;
                o.x = fmaxf(l0 + h0 + bc, 0.0f);
                o.y = fmaxf(l1 + h1 + bc, 0.0f);
                *(float2*)&out[((size_t)(b * R + rec)) * R + s] = o;
            }
        }
    }
}

extern "C" void kernel_launch(void* const* d_in, const int* in_sizes, int n_in,
                              void* d_out, int out_size) {
    (void)in_sizes; (void)n_in; (void)out_size;
    const float* x    = (const float*)d_in[0];  // (16,360,64)
    const float* Wout = (const float*)d_in[1];  // (128,64)
    const float* bout = (const float*)d_in[2];  // (64)
    const float* Wcat = (const float*)d_in[3];  // (64,1)
    const float* bcat = (const float*)d_in[4];  // (1)
    float* out = (float*)d_out;                 // (16,360,360,1) fp32

    k1_uv<<<360, 256>>>(x, Wout, bout);        // 5760 rows / 16

    // PDL launch: k2's launch + non-dependent prologue overlap k1
    cudaLaunchConfig_t cfg = {};
    cfg.gridDim  = dim3(6, 6, 16);
    cfg.blockDim = dim3(256, 1, 1);
    cfg.stream   = 0;
    cudaLaunchAttribute attrs[1];
    attrs[0].id = cudaLaunchAttributeProgrammaticStreamSerialization;
    attrs[0].val.programmaticStreamSerializationAllowed = 1;
    cfg.attrs = attrs;
    cfg.numAttrs = 1;
    cudaLaunchKernelEx(&cfg, k2_pair, Wcat, bcat, out);
}